// round 16
// baseline (speedup 1.0000x reference)
#include <cuda_runtime.h>
#include <cuda_fp16.h>
#include <cstdint>
#include <math.h>

#define NIPV    256
#define NINNER  16
#define NINPUT  784
#define NDIM    64
#define TWO_PI  6.28318530717958647692f
#define NEG_INF __int_as_float(0xff800000)

// ---------------------------------------------------------------------------
__device__ __forceinline__ uint32_t pack_h2(float a, float b) {
    __half2 h = __floats2half2_rn(a, b);
    return *reinterpret_cast<uint32_t*>(&h);
}
__device__ __forceinline__ void mma16(float* c, const uint32_t* a, uint32_t b0, uint32_t b1) {
    asm volatile("mma.sync.aligned.m16n8k16.row.col.f32.f16.f16.f32 "
        "{%0,%1,%2,%3}, {%4,%5,%6,%7}, {%8,%9}, {%0,%1,%2,%3};"
        : "+f"(c[0]), "+f"(c[1]), "+f"(c[2]), "+f"(c[3])
        : "r"(a[0]), "r"(a[1]), "r"(a[2]), "r"(a[3]), "r"(b0), "r"(b1));
}
__device__ __forceinline__ float fast_tanh(float x) {
    float y; asm("tanh.approx.f32 %0, %1;" : "=f"(y) : "f"(x)); return y;
}
__device__ __forceinline__ float softplus_f(float x) {
    return fmaxf(x, 0.f) + log1pf(__expf(-fabsf(x)));
}
__device__ __forceinline__ void load_tile4(float4 v[4], const float* src, int t) {
    const float4* s4 = (const float4*)src;
#pragma unroll
    for (int r = 0; r < 4; r++) v[r] = s4[t + 256 * r];
}
// frag64-xor B layout (2048 u32 words per 64x64 tile); conflict-free loads.
__device__ __forceinline__ void store_tileBTx(uint32_t* dst, const float4 v[4], int t) {
#pragma unroll
    for (int r = 0; r < 4; r++) {
        int f4 = t + 256 * r;
        int col = f4 >> 4, c4 = f4 & 15;
        int cb8 = col >> 3, g8 = col & 7;
        int ks = c4 >> 2, hi = (c4 >> 1) & 1;
        int p0 = ((c4 & 1) << 4) + g8;
        int base = (ks * 8 + cb8) * 64;
        dst[base + 2 * ( p0      ^ (2 * ks)) + hi] = pack_h2(v[r].x, v[r].y);
        dst[base + 2 * ((p0 + 8) ^ (2 * ks)) + hi] = pack_h2(v[r].z, v[r].w);
    }
}

// ===========================================================================
// Inner path. smem words: TB0 2048 | TB1 2048 | w2s 512 | lws 256
//   | vbuf 2080 | lseb 8  = 6952
// ===========================================================================
__device__ void inner_path(float* sm, int bx,
    const float* __restrict__ z, const float* __restrict__ log_w,
    const float* __restrict__ icoef, const float* __restrict__ w1,
    const float* __restrict__ w2, float* __restrict__ out)
{
    uint32_t* TB0 = (uint32_t*)sm;
    uint32_t* TB1 = TB0 + 2048;
    float* w2s  = sm + 4096;
    float* lws  = sm + 4608;
    float* vbuf = sm + 4864;    // [8][260]
    float* lseb = sm + 6944;

    const int t = threadIdx.x, lane = t & 31, w = t >> 5;
    const int gid = lane >> 2, tig = lane & 3;
    const int i = bx >> 1, gh = bx & 1;

    int pk[4];
#pragma unroll
    for (int ks = 0; ks < 4; ks++) pk[ks] = 2 * ((tig * 8 + gid) ^ (2 * ks));

    float4 tr[4];
    load_tile4(tr, w1 + (size_t)(gh * 8) * 4096, t);

    const float zi = z[i];
    float zjv[4];
#pragma unroll
    for (int k = 0; k < 4; k++) zjv[k] = __ldg(z + 32 * w + gid + 8 * k);

    uint32_t af[2][4][4];
#pragma unroll
    for (int ksl = 0; ksl < 2; ksl++)
#pragma unroll
        for (int kh = 0; kh < 2; kh++) {
            int k0 = 16 * ksl + 8 * kh + 2 * tig;
            float c0 = __ldg(icoef + k0),      c1 = __ldg(icoef + k0 + 1);
            float d0 = __ldg(icoef + 32 + k0), d1 = __ldg(icoef + 32 + k0 + 1);
#pragma unroll
            for (int mm = 0; mm < 2; mm++)
#pragma unroll
                for (int ar = 0; ar < 2; ar++) {
                    float s0, co0, s1, co1;
                    __sincosf(TWO_PI * fmaf(zi, c0, zjv[2 * mm + ar] * d0), &s0, &co0);
                    __sincosf(TWO_PI * fmaf(zi, c1, zjv[2 * mm + ar] * d1), &s1, &co1);
                    af[mm][ksl][ar + 2 * kh]     = pack_h2(co0, co1);
                    af[mm][ksl + 2][ar + 2 * kh] = pack_h2(s0, s1);
                }
        }

    for (int idx = t; idx < 512; idx += 256) w2s[idx] = w2[gh * 512 + idx];
    lws[t] = log_w[t];
    store_tileBTx(TB0, tr, t);
    __syncthreads();

#pragma unroll 1
    for (int gl = 0; gl < 8; gl++) {
        const uint32_t* TB = (gl & 1) ? TB1 : TB0;
        if (gl < 7) load_tile4(tr, w1 + (size_t)(gh * 8 + gl + 1) * 4096, t);

        float pc[2][2] = {{0.f, 0.f}, {0.f, 0.f}};
#pragma unroll
        for (int q = 0; q < 4; q++) {
            float C[2][2][4];
#pragma unroll
            for (int mm = 0; mm < 2; mm++)
#pragma unroll
                for (int nb = 0; nb < 2; nb++)
#pragma unroll
                    for (int jj = 0; jj < 4; jj++) C[mm][nb][jj] = 0.f;
#pragma unroll
            for (int ks = 0; ks < 4; ks++)
#pragma unroll
                for (int nb = 0; nb < 2; nb++) {
                    uint2 b = *(const uint2*)(TB + (ks * 8 + 2 * q + nb) * 64 + pk[ks]);
                    mma16(C[0][nb], af[0][ks], b.x, b.y);
                    mma16(C[1][nb], af[1][ks], b.x, b.y);
                }
#pragma unroll
            for (int mm = 0; mm < 2; mm++)
#pragma unroll
                for (int nb = 0; nb < 2; nb++)
#pragma unroll
                    for (int jj = 0; jj < 4; jj++) {
                        int d = 16 * q + 8 * nb + 2 * tig + (jj & 1);
                        pc[mm][jj >> 1] += w2s[gl * 64 + d] * fast_tanh(C[mm][nb][jj]);
                    }
        }
#pragma unroll
        for (int mm = 0; mm < 2; mm++)
#pragma unroll
            for (int ar = 0; ar < 2; ar++) {
                pc[mm][ar] += __shfl_xor_sync(0xffffffffu, pc[mm][ar], 1);
                pc[mm][ar] += __shfl_xor_sync(0xffffffffu, pc[mm][ar], 2);
            }
        if (tig == 0) {
#pragma unroll
            for (int mm = 0; mm < 2; mm++)
#pragma unroll
                for (int ar = 0; ar < 2; ar++) {
                    int j = 32 * w + 16 * mm + 8 * ar + gid;
                    vbuf[gl * 260 + j] = lws[j] - softplus_f(pc[mm][ar]);
                }
        }
        if (gl < 7) store_tileBTx((gl & 1) ? TB0 : TB1, tr, t);
        __syncthreads();
    }

    {
        const float* row = vbuf + w * 260;
        float mx = NEG_INF;
#pragma unroll
        for (int k = 0; k < 8; k++) mx = fmaxf(mx, row[lane + 32 * k]);
#pragma unroll
        for (int o = 16; o > 0; o >>= 1) mx = fmaxf(mx, __shfl_xor_sync(0xffffffffu, mx, o));
        float ssum = 0.f;
#pragma unroll
        for (int k = 0; k < 8; k++) ssum += __expf(row[lane + 32 * k] - mx);
#pragma unroll
        for (int o = 16; o > 0; o >>= 1) ssum += __shfl_xor_sync(0xffffffffu, ssum, o);
        if (lane == 0) lseb[w] = mx + __logf(ssum);
    }
    __syncthreads();

#pragma unroll
    for (int lg = 0; lg < 8; lg++)
        out[(size_t)(gh * 8 + lg) * (NIPV * NIPV) + (size_t)t * NIPV + i] =
            __expf(vbuf[lg * 260 + t] - lseb[lg]);
}

// ===========================================================================
// Input path: 4 w2 chunks resident; pass A = plain sum-of-exp (logits are
// bounded, |v| <~ 10, so no max subtraction needed); pass B = write with
// subtract. smem words: TBall 4*2048 = 8192 | his 8448  = 16640
// ===========================================================================
__device__ void input_path(float* sm, int g,
    const float* __restrict__ z, const float* __restrict__ icoef,
    const float* __restrict__ w1, const float* __restrict__ w2,
    float* __restrict__ out)
{
    uint32_t* TBall = (uint32_t*)sm;          // 4 x 2048 (slot0 = w1 first)
    uint32_t* his   = (uint32_t*)sm + 8192;   // [32 dp][264] half2

    const int t = threadIdx.x, lane = t & 31, w = t >> 5;
    const int gid = lane >> 2, tig = lane & 3;
    const float* w2g = w2 + (size_t)g * 16384;

    int pk[4];
#pragma unroll
    for (int ks = 0; ks < 4; ks++) pk[ks] = 2 * ((tig * 8 + gid) ^ (2 * ks));

    float4 tr[4];
    load_tile4(tr, w1 + (size_t)g * 4096, t);
    store_tileBTx(TBall, tr, t);              // w1 -> slot 0
    load_tile4(tr, w2g + 4096, t);            // chunk 1 LDG

    float zjv[4];
#pragma unroll
    for (int k = 0; k < 4; k++) zjv[k] = __ldg(z + 32 * w + gid + 8 * k);

    uint32_t af[2][4][4];
#pragma unroll
    for (int ksl = 0; ksl < 2; ksl++)
#pragma unroll
        for (int kh = 0; kh < 2; kh++) {
            int k0 = 16 * ksl + 8 * kh + 2 * tig;
            float c0 = __ldg(icoef + k0), c1 = __ldg(icoef + k0 + 1);
#pragma unroll
            for (int mm = 0; mm < 2; mm++)
#pragma unroll
                for (int ar = 0; ar < 2; ar++) {
                    float s0, co0, s1, co1;
                    __sincosf(TWO_PI * zjv[2 * mm + ar] * c0, &s0, &co0);
                    __sincosf(TWO_PI * zjv[2 * mm + ar] * c1, &s1, &co1);
                    af[mm][ksl][ar + 2 * kh]     = pack_h2(co0, co1);
                    af[mm][ksl + 2][ar + 2 * kh] = pack_h2(s0, s1);
                }
        }

    store_tileBTx(TBall + 2048, tr, t);       // chunk 1 -> slot 1
    load_tile4(tr, w2g + 8192, t);
    store_tileBTx(TBall + 2 * 2048, tr, t);   // chunk 2 -> slot 2
    load_tile4(tr, w2g + 12288, t);
    store_tileBTx(TBall + 3 * 2048, tr, t);   // chunk 3 -> slot 3
    __syncthreads();                          // slot 0 (w1) visible

    // ---- stage 1: C[n][d] quarters -> tanh -> his[dp][n]
#pragma unroll
    for (int q = 0; q < 4; q++) {
        float C[2][2][4];
#pragma unroll
        for (int mm = 0; mm < 2; mm++)
#pragma unroll
            for (int nb = 0; nb < 2; nb++)
#pragma unroll
                for (int jj = 0; jj < 4; jj++) C[mm][nb][jj] = 0.f;
#pragma unroll
        for (int ks = 0; ks < 4; ks++)
#pragma unroll
            for (int nb = 0; nb < 2; nb++) {
                uint2 b = *(const uint2*)(TBall + (ks * 8 + 2 * q + nb) * 64 + pk[ks]);
                mma16(C[0][nb], af[0][ks], b.x, b.y);
                mma16(C[1][nb], af[1][ks], b.x, b.y);
            }
#pragma unroll
        for (int mm = 0; mm < 2; mm++)
#pragma unroll
            for (int nb = 0; nb < 2; nb++)
#pragma unroll
                for (int rr = 0; rr < 2; rr++) {
                    int dp = 8 * q + 4 * nb + tig;
                    int n = 32 * w + 16 * mm + 8 * rr + gid;
                    his[dp * 264 + n] = pack_h2(fast_tanh(C[mm][nb][2 * rr]),
                                                fast_tanh(C[mm][nb][2 * rr + 1]));
                }
    }
    load_tile4(tr, w2g, t);                   // chunk 0 LDG
    __syncthreads();                          // his complete; slot-0 reads done

    uint32_t af2[2][4][4];
#pragma unroll
    for (int mm = 0; mm < 2; mm++)
#pragma unroll
        for (int ks = 0; ks < 4; ks++)
#pragma unroll
            for (int kh = 0; kh < 2; kh++)
#pragma unroll
                for (int ar = 0; ar < 2; ar++)
                    af2[mm][ks][ar + 2 * kh] =
                        his[(8 * ks + 4 * kh + tig) * 264 + 32 * w + 16 * mm + 8 * ar + gid];

    store_tileBTx(TBall, tr, t);              // chunk 0 -> slot 0
    __syncthreads();                          // all 4 chunks resident

    // ---- pass A: plain sum of exp (no max subtraction; logits bounded)
    float srow[4] = {0.f, 0.f, 0.f, 0.f};

#pragma unroll 1
    for (int cb = 0; cb < 4; cb++) {
        const uint32_t* TB = TBall + cb * 2048;
#pragma unroll
        for (int q = 0; q < 4; q++) {
            float C[2][2][4];
#pragma unroll
            for (int mm = 0; mm < 2; mm++)
#pragma unroll
                for (int nb = 0; nb < 2; nb++)
#pragma unroll
                    for (int jj = 0; jj < 4; jj++) C[mm][nb][jj] = 0.f;
#pragma unroll
            for (int ks = 0; ks < 4; ks++)
#pragma unroll
                for (int nb = 0; nb < 2; nb++) {
                    uint2 b = *(const uint2*)(TB + (ks * 8 + 2 * q + nb) * 64 + pk[ks]);
                    mma16(C[0][nb], af2[0][ks], b.x, b.y);
                    mma16(C[1][nb], af2[1][ks], b.x, b.y);
                }
            // quarter-local tree sum per row, then one add to the accumulator
#pragma unroll
            for (int mm = 0; mm < 2; mm++)
#pragma unroll
                for (int rr = 0; rr < 2; rr++) {
                    float e0 = __expf(C[mm][0][2 * rr])     + __expf(C[mm][1][2 * rr]);
                    float e1 = __expf(C[mm][0][2 * rr + 1]) + __expf(C[mm][1][2 * rr + 1]);
                    srow[2 * mm + rr] += e0 + e1;
                }
        }
    }
    float lse[4];
#pragma unroll
    for (int r = 0; r < 4; r++) {
        srow[r] += __shfl_xor_sync(0xffffffffu, srow[r], 1);
        srow[r] += __shfl_xor_sync(0xffffffffu, srow[r], 2);
        lse[r] = __logf(srow[r]);
    }

    // ---- pass B: recompute and write (C - lse) via STG.64
    float* og = out + (size_t)g * (NIPV * 256);
#pragma unroll 1
    for (int cb = 0; cb < 4; cb++) {
        const uint32_t* TB = TBall + cb * 2048;
#pragma unroll
        for (int q = 0; q < 4; q++) {
            float C[2][2][4];
#pragma unroll
            for (int mm = 0; mm < 2; mm++)
#pragma unroll
                for (int nb = 0; nb < 2; nb++)
#pragma unroll
                    for (int jj = 0; jj < 4; jj++) C[mm][nb][jj] = 0.f;
#pragma unroll
            for (int ks = 0; ks < 4; ks++)
#pragma unroll
                for (int nb = 0; nb < 2; nb++) {
                    uint2 b = *(const uint2*)(TB + (ks * 8 + 2 * q + nb) * 64 + pk[ks]);
                    mma16(C[0][nb], af2[0][ks], b.x, b.y);
                    mma16(C[1][nb], af2[1][ks], b.x, b.y);
                }
#pragma unroll
            for (int mm = 0; mm < 2; mm++)
#pragma unroll
                for (int rr = 0; rr < 2; rr++) {
                    int n = 32 * w + 16 * mm + 8 * rr + gid;
                    float l = lse[2 * mm + rr];
#pragma unroll
                    for (int nb = 0; nb < 2; nb++) {
                        float2 v;
                        v.x = C[mm][nb][2 * rr]     - l;
                        v.y = C[mm][nb][2 * rr + 1] - l;
                        *(float2*)(og + (size_t)n * 256 + cb * 64 + q * 16 + 8 * nb + 2 * tig) = v;
                    }
                }
        }
    }
}

// ===========================================================================
__global__ __launch_bounds__(256, 3) void mega2_kernel(
    const float* __restrict__ z, const float* __restrict__ log_w,
    const float* __restrict__ icoef, const float* __restrict__ iw1,
    const float* __restrict__ iw2,
    const float* __restrict__ incoef, const float* __restrict__ inw1,
    const float* __restrict__ inw2,
    float* __restrict__ out_inner, float* __restrict__ out_input)
{
    extern __shared__ float sm[];
    if (blockIdx.x < 512)
        inner_path(sm, blockIdx.x, z, log_w, icoef, iw1, iw2, out_inner);
    else
        input_path(sm, blockIdx.x - 512, z, incoef, inw1, inw2, out_input);
}

extern "C" void kernel_launch(void* const* d_in, const int* in_sizes, int n_in,
                              void* d_out, int out_size) {
    const float* z      = (const float*)d_in[0];
    const float* log_w  = (const float*)d_in[1];
    const float* icoef  = (const float*)d_in[2];
    const float* iw1    = (const float*)d_in[3];
    const float* iw2    = (const float*)d_in[4];
    const float* incoef = (const float*)d_in[5];
    const float* inw1   = (const float*)d_in[6];
    const float* inw2   = (const float*)d_in[7];

    float* out = (float*)d_out;
    float* out_input = out + (size_t)NINNER * NIPV * NIPV;

    const int SMEM = 16640 * (int)sizeof(float);   // 66,560 B
    cudaFuncSetAttribute(mega2_kernel, cudaFuncAttributeMaxDynamicSharedMemorySize, SMEM);

    mega2_kernel<<<512 + NINPUT, 256, SMEM>>>(z, log_w, icoef, iw1, iw2,
                                              incoef, inw1, inw2, out, out_input);
}

// round 17
// speedup vs baseline: 1.0937x; 1.0937x over previous
#include <cuda_runtime.h>
#include <cuda_fp16.h>
#include <cstdint>
#include <math.h>

#define NIPV    256
#define NINNER  16
#define NINPUT  784
#define NDIM    64
#define TWO_PI  6.28318530717958647692f
#define NEG_INF __int_as_float(0xff800000)

// ---------------------------------------------------------------------------
__device__ __forceinline__ uint32_t pack_h2(float a, float b) {
    __half2 h = __floats2half2_rn(a, b);
    return *reinterpret_cast<uint32_t*>(&h);
}
__device__ __forceinline__ void mma16(float* c, const uint32_t* a, uint32_t b0, uint32_t b1) {
    asm volatile("mma.sync.aligned.m16n8k16.row.col.f32.f16.f16.f32 "
        "{%0,%1,%2,%3}, {%4,%5,%6,%7}, {%8,%9}, {%0,%1,%2,%3};"
        : "+f"(c[0]), "+f"(c[1]), "+f"(c[2]), "+f"(c[3])
        : "r"(a[0]), "r"(a[1]), "r"(a[2]), "r"(a[3]), "r"(b0), "r"(b1));
}
__device__ __forceinline__ float fast_tanh(float x) {
    float y; asm("tanh.approx.f32 %0, %1;" : "=f"(y) : "f"(x)); return y;
}
__device__ __forceinline__ float softplus_f(float x) {
    return fmaxf(x, 0.f) + log1pf(__expf(-fabsf(x)));
}
__device__ __forceinline__ void load_tile4(float4 v[4], const float* src, int t) {
    const float4* s4 = (const float4*)src;
#pragma unroll
    for (int r = 0; r < 4; r++) v[r] = s4[t + 256 * r];
}
// frag64-xor B layout (2048 u32 words per 64x64 tile); conflict-free loads.
__device__ __forceinline__ void store_tileBTx(uint32_t* dst, const float4 v[4], int t) {
#pragma unroll
    for (int r = 0; r < 4; r++) {
        int f4 = t + 256 * r;
        int col = f4 >> 4, c4 = f4 & 15;
        int cb8 = col >> 3, g8 = col & 7;
        int ks = c4 >> 2, hi = (c4 >> 1) & 1;
        int p0 = ((c4 & 1) << 4) + g8;
        int base = (ks * 8 + cb8) * 64;
        dst[base + 2 * ( p0      ^ (2 * ks)) + hi] = pack_h2(v[r].x, v[r].y);
        dst[base + 2 * ((p0 + 8) ^ (2 * ks)) + hi] = pack_h2(v[r].z, v[r].w);
    }
}

// ===========================================================================
// Inner path (mm=4): warp = (rgrp = w&3 -> 64 j-rows, wq = w>>2 -> d-half).
// smem words: TB0 2048 | TB1 2048 | w2s 512 | lws 256 | vbp 2*2080 | lseb 8
//   = 9032
// ===========================================================================
__device__ void inner_path(float* sm, int bx,
    const float* __restrict__ z, const float* __restrict__ log_w,
    const float* __restrict__ icoef, const float* __restrict__ w1,
    const float* __restrict__ w2, float* __restrict__ out)
{
    uint32_t* TB0 = (uint32_t*)sm;
    uint32_t* TB1 = TB0 + 2048;
    float* w2s  = sm + 4096;
    float* lws  = sm + 4608;
    float* vbp  = sm + 4864;    // [2 wq][8 gl][260]
    float* lseb = sm + 9024;

    const int t = threadIdx.x, lane = t & 31, w = t >> 5;
    const int gid = lane >> 2, tig = lane & 3;
    const int rgrp = w & 3, wq = w >> 2;
    const int i = bx >> 1, gh = bx & 1;

    int pk[4];
#pragma unroll
    for (int ks = 0; ks < 4; ks++) pk[ks] = 2 * ((tig * 8 + gid) ^ (2 * ks));

    float4 tr[4];
    load_tile4(tr, w1 + (size_t)(gh * 8) * 4096, t);

    const float zi = z[i];
    float zjv[8];
#pragma unroll
    for (int mm = 0; mm < 4; mm++)
#pragma unroll
        for (int ar = 0; ar < 2; ar++)
            zjv[mm * 2 + ar] = __ldg(z + rgrp * 64 + mm * 16 + ar * 8 + gid);

    uint32_t af[4][4][4];
#pragma unroll
    for (int ksl = 0; ksl < 2; ksl++)
#pragma unroll
        for (int kh = 0; kh < 2; kh++) {
            int k0 = 16 * ksl + 8 * kh + 2 * tig;
            float c0 = __ldg(icoef + k0),      c1 = __ldg(icoef + k0 + 1);
            float d0 = __ldg(icoef + 32 + k0), d1 = __ldg(icoef + 32 + k0 + 1);
#pragma unroll
            for (int mm = 0; mm < 4; mm++)
#pragma unroll
                for (int ar = 0; ar < 2; ar++) {
                    float s0, co0, s1, co1;
                    __sincosf(TWO_PI * fmaf(zi, c0, zjv[2 * mm + ar] * d0), &s0, &co0);
                    __sincosf(TWO_PI * fmaf(zi, c1, zjv[2 * mm + ar] * d1), &s1, &co1);
                    af[mm][ksl][ar + 2 * kh]     = pack_h2(co0, co1);
                    af[mm][ksl + 2][ar + 2 * kh] = pack_h2(s0, s1);
                }
        }

    for (int idx = t; idx < 512; idx += 256) w2s[idx] = w2[gh * 512 + idx];
    lws[t] = log_w[t];
    store_tileBTx(TB0, tr, t);
    __syncthreads();

#pragma unroll 1
    for (int gl = 0; gl < 8; gl++) {
        const uint32_t* TB = (gl & 1) ? TB1 : TB0;

        float pc[4][2] = {{0,0},{0,0},{0,0},{0,0}};
#pragma unroll
        for (int qi = 0; qi < 2; qi++) {
            const int q = 2 * wq + qi;
            float C[4][2][4];
#pragma unroll
            for (int mm = 0; mm < 4; mm++)
#pragma unroll
                for (int nb = 0; nb < 2; nb++)
#pragma unroll
                    for (int jj = 0; jj < 4; jj++) C[mm][nb][jj] = 0.f;
#pragma unroll
            for (int ks = 0; ks < 4; ks++)
#pragma unroll
                for (int nb = 0; nb < 2; nb++) {
                    uint2 b = *(const uint2*)(TB + (ks * 8 + 2 * q + nb) * 64 + pk[ks]);
#pragma unroll
                    for (int mm = 0; mm < 4; mm++) mma16(C[mm][nb], af[mm][ks], b.x, b.y);
                }
#pragma unroll
            for (int mm = 0; mm < 4; mm++)
#pragma unroll
                for (int nb = 0; nb < 2; nb++)
#pragma unroll
                    for (int jj = 0; jj < 4; jj++) {
                        int d = 16 * q + 8 * nb + 2 * tig + (jj & 1);
                        pc[mm][jj >> 1] += w2s[gl * 64 + d] * fast_tanh(C[mm][nb][jj]);
                    }
        }
        if (gl < 7) load_tile4(tr, w1 + (size_t)(gh * 8 + gl + 1) * 4096, t);
#pragma unroll
        for (int mm = 0; mm < 4; mm++)
#pragma unroll
            for (int ar = 0; ar < 2; ar++) {
                pc[mm][ar] += __shfl_xor_sync(0xffffffffu, pc[mm][ar], 1);
                pc[mm][ar] += __shfl_xor_sync(0xffffffffu, pc[mm][ar], 2);
            }
        if (tig == 0) {
#pragma unroll
            for (int mm = 0; mm < 4; mm++)
#pragma unroll
                for (int ar = 0; ar < 2; ar++) {
                    int j = rgrp * 64 + 16 * mm + 8 * ar + gid;
                    vbp[wq * 2080 + gl * 260 + j] = pc[mm][ar];
                }
        }
        if (gl < 7) store_tileBTx((gl & 1) ? TB0 : TB1, tr, t);
        __syncthreads();
    }

    // combine wq halves -> logits (overwrite wq=0 half)
#pragma unroll
    for (int gl = 0; gl < 8; gl++) {
        float acc = vbp[gl * 260 + t] + vbp[2080 + gl * 260 + t];
        vbp[gl * 260 + t] = lws[t] - softplus_f(acc);
    }
    __syncthreads();

    {   // lse over j per g: warp w handles row w
        const float* row = vbp + w * 260;
        float mx = NEG_INF;
#pragma unroll
        for (int k = 0; k < 8; k++) mx = fmaxf(mx, row[lane + 32 * k]);
#pragma unroll
        for (int o = 16; o > 0; o >>= 1) mx = fmaxf(mx, __shfl_xor_sync(0xffffffffu, mx, o));
        float ssum = 0.f;
#pragma unroll
        for (int k = 0; k < 8; k++) ssum += __expf(row[lane + 32 * k] - mx);
#pragma unroll
        for (int o = 16; o > 0; o >>= 1) ssum += __shfl_xor_sync(0xffffffffu, ssum, o);
        if (lane == 0) lseb[w] = mx + __logf(ssum);
    }
    __syncthreads();

#pragma unroll
    for (int lg = 0; lg < 8; lg++)
        out[(size_t)(gh * 8 + lg) * (NIPV * NIPV) + (size_t)t * NIPV + i] =
            __expf(vbp[lg * 260 + t] - lseb[lg]);
}

// ===========================================================================
// Input path (mm=4): pass A = exp-sums (bounded logits), pass B = write-sub.
// smem words: TBall 4*2048 = 8192 | his 8448 | lsp 512 | lseb 256 = 17408
// ===========================================================================
__device__ void input_path(float* sm, int g,
    const float* __restrict__ z, const float* __restrict__ icoef,
    const float* __restrict__ w1, const float* __restrict__ w2,
    float* __restrict__ out)
{
    uint32_t* TBall = (uint32_t*)sm;          // 4 x 2048 (slot0 = w1 first)
    uint32_t* his   = (uint32_t*)sm + 8192;   // [32 dp][264] half2
    float* lsp  = sm + 16640;                 // [2 wq][256 n]
    float* lseb = sm + 17152;                 // [256]

    const int t = threadIdx.x, lane = t & 31, w = t >> 5;
    const int gid = lane >> 2, tig = lane & 3;
    const int rgrp = w & 3, wq = w >> 2;
    const float* w2g = w2 + (size_t)g * 16384;

    int pk[4];
#pragma unroll
    for (int ks = 0; ks < 4; ks++) pk[ks] = 2 * ((tig * 8 + gid) ^ (2 * ks));

    float4 tr[4];
    load_tile4(tr, w1 + (size_t)g * 4096, t);
    store_tileBTx(TBall, tr, t);              // w1 -> slot 0
    load_tile4(tr, w2g + 4096, t);            // chunk 1 LDG

    float zjv[8];
#pragma unroll
    for (int mm = 0; mm < 4; mm++)
#pragma unroll
        for (int ar = 0; ar < 2; ar++)
            zjv[mm * 2 + ar] = __ldg(z + rgrp * 64 + mm * 16 + ar * 8 + gid);

    uint32_t af[4][4][4];
#pragma unroll
    for (int ksl = 0; ksl < 2; ksl++)
#pragma unroll
        for (int kh = 0; kh < 2; kh++) {
            int k0 = 16 * ksl + 8 * kh + 2 * tig;
            float c0 = __ldg(icoef + k0), c1 = __ldg(icoef + k0 + 1);
#pragma unroll
            for (int mm = 0; mm < 4; mm++)
#pragma unroll
                for (int ar = 0; ar < 2; ar++) {
                    float s0, co0, s1, co1;
                    __sincosf(TWO_PI * zjv[2 * mm + ar] * c0, &s0, &co0);
                    __sincosf(TWO_PI * zjv[2 * mm + ar] * c1, &s1, &co1);
                    af[mm][ksl][ar + 2 * kh]     = pack_h2(co0, co1);
                    af[mm][ksl + 2][ar + 2 * kh] = pack_h2(s0, s1);
                }
        }

    store_tileBTx(TBall + 2048, tr, t);       // chunk 1 -> slot 1
    load_tile4(tr, w2g + 8192, t);
    store_tileBTx(TBall + 2 * 2048, tr, t);   // chunk 2 -> slot 2
    load_tile4(tr, w2g + 12288, t);
    store_tileBTx(TBall + 3 * 2048, tr, t);   // chunk 3 -> slot 3
    __syncthreads();                          // slot 0 (w1) visible

    // ---- stage 1: C[n][d] (warp's d-half) -> tanh -> his[dp][n]
#pragma unroll
    for (int qi = 0; qi < 2; qi++) {
        const int q = 2 * wq + qi;
        float C[4][2][4];
#pragma unroll
        for (int mm = 0; mm < 4; mm++)
#pragma unroll
            for (int nb = 0; nb < 2; nb++)
#pragma unroll
                for (int jj = 0; jj < 4; jj++) C[mm][nb][jj] = 0.f;
#pragma unroll
        for (int ks = 0; ks < 4; ks++)
#pragma unroll
            for (int nb = 0; nb < 2; nb++) {
                uint2 b = *(const uint2*)(TBall + (ks * 8 + 2 * q + nb) * 64 + pk[ks]);
#pragma unroll
                for (int mm = 0; mm < 4; mm++) mma16(C[mm][nb], af[mm][ks], b.x, b.y);
            }
#pragma unroll
        for (int mm = 0; mm < 4; mm++)
#pragma unroll
            for (int nb = 0; nb < 2; nb++)
#pragma unroll
                for (int rr = 0; rr < 2; rr++) {
                    int dp = 8 * q + 4 * nb + tig;
                    int n = rgrp * 64 + 16 * mm + 8 * rr + gid;
                    his[dp * 264 + n] = pack_h2(fast_tanh(C[mm][nb][2 * rr]),
                                                fast_tanh(C[mm][nb][2 * rr + 1]));
                }
    }
    load_tile4(tr, w2g, t);                   // chunk 0 LDG
    __syncthreads();                          // his complete; slot-0 reads done

    uint32_t af2[4][4][4];
#pragma unroll
    for (int mm = 0; mm < 4; mm++)
#pragma unroll
        for (int ks = 0; ks < 4; ks++)
#pragma unroll
            for (int kh = 0; kh < 2; kh++)
#pragma unroll
                for (int ar = 0; ar < 2; ar++)
                    af2[mm][ks][ar + 2 * kh] =
                        his[(8 * ks + 4 * kh + tig) * 264 + rgrp * 64 + 16 * mm + 8 * ar + gid];

    store_tileBTx(TBall, tr, t);              // chunk 0 -> slot 0
    __syncthreads();                          // all 4 chunks resident

    // ---- pass A: plain sum of exp over warp's column half
    float srow[8];
#pragma unroll
    for (int r = 0; r < 8; r++) srow[r] = 0.f;

#pragma unroll 1
    for (int cb = 0; cb < 4; cb++) {
        const uint32_t* TB = TBall + cb * 2048;
#pragma unroll
        for (int qi = 0; qi < 2; qi++) {
            const int q = 2 * wq + qi;
            float C[4][2][4];
#pragma unroll
            for (int mm = 0; mm < 4; mm++)
#pragma unroll
                for (int nb = 0; nb < 2; nb++)
#pragma unroll
                    for (int jj = 0; jj < 4; jj++) C[mm][nb][jj] = 0.f;
#pragma unroll
            for (int ks = 0; ks < 4; ks++)
#pragma unroll
                for (int nb = 0; nb < 2; nb++) {
                    uint2 b = *(const uint2*)(TB + (ks * 8 + 2 * q + nb) * 64 + pk[ks]);
#pragma unroll
                    for (int mm = 0; mm < 4; mm++) mma16(C[mm][nb], af2[mm][ks], b.x, b.y);
                }
#pragma unroll
            for (int mm = 0; mm < 4; mm++)
#pragma unroll
                for (int rr = 0; rr < 2; rr++) {
                    float e0 = __expf(C[mm][0][2 * rr])     + __expf(C[mm][1][2 * rr]);
                    float e1 = __expf(C[mm][0][2 * rr + 1]) + __expf(C[mm][1][2 * rr + 1]);
                    srow[2 * mm + rr] += e0 + e1;
                }
        }
    }
#pragma unroll
    for (int r = 0; r < 8; r++) {
        srow[r] += __shfl_xor_sync(0xffffffffu, srow[r], 1);
        srow[r] += __shfl_xor_sync(0xffffffffu, srow[r], 2);
    }
    if (tig == 0) {
#pragma unroll
        for (int mm = 0; mm < 4; mm++)
#pragma unroll
            for (int rr = 0; rr < 2; rr++)
                lsp[wq * 256 + rgrp * 64 + 16 * mm + 8 * rr + gid] = srow[2 * mm + rr];
    }
    __syncthreads();
    lseb[t] = __logf(lsp[t] + lsp[256 + t]);
    __syncthreads();

    float lseR[8];
#pragma unroll
    for (int mm = 0; mm < 4; mm++)
#pragma unroll
        for (int rr = 0; rr < 2; rr++)
            lseR[2 * mm + rr] = lseb[rgrp * 64 + 16 * mm + 8 * rr + gid];

    // ---- pass B: recompute and write (C - lse) via STG.64
    float* og = out + (size_t)g * (NIPV * 256);
#pragma unroll 1
    for (int cb = 0; cb < 4; cb++) {
        const uint32_t* TB = TBall + cb * 2048;
#pragma unroll
        for (int qi = 0; qi < 2; qi++) {
            const int q = 2 * wq + qi;
            float C[4][2][4];
#pragma unroll
            for (int mm = 0; mm < 4; mm++)
#pragma unroll
                for (int nb = 0; nb < 2; nb++)
#pragma unroll
                    for (int jj = 0; jj < 4; jj++) C[mm][nb][jj] = 0.f;
#pragma unroll
            for (int ks = 0; ks < 4; ks++)
#pragma unroll
                for (int nb = 0; nb < 2; nb++) {
                    uint2 b = *(const uint2*)(TB + (ks * 8 + 2 * q + nb) * 64 + pk[ks]);
#pragma unroll
                    for (int mm = 0; mm < 4; mm++) mma16(C[mm][nb], af2[mm][ks], b.x, b.y);
                }
#pragma unroll
            for (int mm = 0; mm < 4; mm++)
#pragma unroll
                for (int rr = 0; rr < 2; rr++) {
                    int n = rgrp * 64 + 16 * mm + 8 * rr + gid;
                    float l = lseR[2 * mm + rr];
#pragma unroll
                    for (int nb = 0; nb < 2; nb++) {
                        float2 v;
                        v.x = C[mm][nb][2 * rr]     - l;
                        v.y = C[mm][nb][2 * rr + 1] - l;
                        *(float2*)(og + (size_t)n * 256 + cb * 64 + q * 16 + 8 * nb + 2 * tig) = v;
                    }
                }
        }
    }
}

// ===========================================================================
__global__ __launch_bounds__(256, 2) void mega2_kernel(
    const float* __restrict__ z, const float* __restrict__ log_w,
    const float* __restrict__ icoef, const float* __restrict__ iw1,
    const float* __restrict__ iw2,
    const float* __restrict__ incoef, const float* __restrict__ inw1,
    const float* __restrict__ inw2,
    float* __restrict__ out_inner, float* __restrict__ out_input)
{
    extern __shared__ float sm[];
    if (blockIdx.x < 512)
        inner_path(sm, blockIdx.x, z, log_w, icoef, iw1, iw2, out_inner);
    else
        input_path(sm, blockIdx.x - 512, z, incoef, inw1, inw2, out_input);
}

extern "C" void kernel_launch(void* const* d_in, const int* in_sizes, int n_in,
                              void* d_out, int out_size) {
    const float* z      = (const float*)d_in[0];
    const float* log_w  = (const float*)d_in[1];
    const float* icoef  = (const float*)d_in[2];
    const float* iw1    = (const float*)d_in[3];
    const float* iw2    = (const float*)d_in[4];
    const float* incoef = (const float*)d_in[5];
    const float* inw1   = (const float*)d_in[6];
    const float* inw2   = (const float*)d_in[7];

    float* out = (float*)d_out;
    float* out_input = out + (size_t)NINNER * NIPV * NIPV;

    const int SMEM = 17408 * (int)sizeof(float);   // 69,632 B
    cudaFuncSetAttribute(mega2_kernel, cudaFuncAttributeMaxDynamicSharedMemorySize, SMEM);

    mega2_kernel<<<512 + NINPUT, 256, SMEM>>>(z, log_w, icoef, iw1, iw2,
                                              incoef, inw1, inw2, out, out_input);
}